// round 14
// baseline (speedup 1.0000x reference)
#include <cuda_runtime.h>
#include <cuda_fp16.h>
#include <cstdint>

// ---------------- problem constants ----------------
constexpr int KC = 128, KH = 10, KW = 4;
constexpr int H = 100, W = 64;
constexpr int HW = H * W;                  // 6400
constexpr int NH = 10, NW = 16;
constexpr int M = NH * NW;                 // 160 q rows
constexpr int HK = H - KH + 1;             // 91
constexpr int WK = W - KW + 1;             // 61
constexpr int NKV = HK * WK;               // 5551
constexpr int NPAD = 5632;                 // 88*64
constexpr int D = KC * KH * KW;            // 5120
constexpr int NT1 = NPAD / 64;             // 88 qk n-tiles

// Feature ordering: d = (i*4+j)*128 + c   (ij-major, channel-fast)

// ---------------- scratch ----------------
__device__ __half g_z1t[(size_t)HW * KC];      // [hw][c] channel-fast
__device__ __half g_z2t[(size_t)HW * KC];
__device__ __half g_kv[(size_t)NPAD * D];      // [n][d]
__device__ __half g_q[M * D];
__device__ __half g_attn[M * NPAD];            // unnormalized exp(scores), pads = 0
__device__ float  g_rsum2[M][NT1];             // per-(row, n-tile) partial sums
__device__ float  g_outp[2][(size_t)M * D];    // split-K partials for attn@kv

// ---------------- ptx helpers ----------------
__device__ __forceinline__ uint32_t smem_u32(const void* p) {
    return (uint32_t)__cvta_generic_to_shared(p);
}
__device__ __forceinline__ void ldsm_x4(uint32_t& r0, uint32_t& r1, uint32_t& r2,
                                        uint32_t& r3, uint32_t a) {
    asm volatile("ldmatrix.sync.aligned.m8n8.x4.shared.b16 {%0,%1,%2,%3}, [%4];"
                 : "=r"(r0), "=r"(r1), "=r"(r2), "=r"(r3) : "r"(a));
}
__device__ __forceinline__ void ldsm_x4_t(uint32_t& r0, uint32_t& r1, uint32_t& r2,
                                          uint32_t& r3, uint32_t a) {
    asm volatile("ldmatrix.sync.aligned.m8n8.x4.trans.shared.b16 {%0,%1,%2,%3}, [%4];"
                 : "=r"(r0), "=r"(r1), "=r"(r2), "=r"(r3) : "r"(a));
}
__device__ __forceinline__ void mma16816(float* c, const uint32_t* a, const uint32_t* b) {
    asm volatile("mma.sync.aligned.m16n8k16.row.col.f32.f16.f16.f32 "
                 "{%0,%1,%2,%3}, {%4,%5,%6,%7}, {%8,%9}, {%0,%1,%2,%3};"
                 : "+f"(c[0]), "+f"(c[1]), "+f"(c[2]), "+f"(c[3])
                 : "r"(a[0]), "r"(a[1]), "r"(a[2]), "r"(a[3]),
                   "r"(b[0]), "r"(b[1]));
}
__device__ __forceinline__ void cpasync16(uint32_t s, const void* g) {
    asm volatile("cp.async.cg.shared.global [%0], [%1], 16;" :: "r"(s), "l"(g));
}
__device__ __forceinline__ void cpasync16_ca(uint32_t s, const void* g) {
    asm volatile("cp.async.ca.shared.global [%0], [%1], 16;" :: "r"(s), "l"(g));
}
#define CP_COMMIT() asm volatile("cp.async.commit_group;")
#define CP_WAIT(n)  asm volatile("cp.async.wait_group %0;" :: "n"(n))

// ------- kernel 0: transpose z1/z2 [c][hw] f32 -> [hw][c] f16 -------
__global__ __launch_bounds__(256) void transpose_kernel(const float* __restrict__ z1,
                                                        const float* __restrict__ z2) {
    __shared__ float tile[32][33];
    const float* src = blockIdx.z ? z2 : z1;
    __half* dst      = blockIdx.z ? g_z2t : g_z1t;
    const int hw0 = blockIdx.x * 32;
    const int c0  = blockIdx.y * 32;
    const int tx = threadIdx.x & 31;
    const int ty = threadIdx.x >> 5;               // 0..7
#pragma unroll
    for (int k = 0; k < 4; k++)
        tile[ty + 8 * k][tx] = src[(size_t)(c0 + ty + 8 * k) * HW + hw0 + tx];
    __syncthreads();
#pragma unroll
    for (int k = 0; k < 4; k++)
        dst[(size_t)(hw0 + ty + 8 * k) * KC + c0 + tx] =
            __float2half(tile[tx][ty + 8 * k]);
}

// ------- kernel 1: build q + kv, fully coalesced 16B chunks -------
constexpr int CH_ROW = D / 8;                          // 640 chunks per row
constexpr int KV16  = NKV * CH_ROW;                    // 3,552,640
constexpr int PAD16 = (NPAD - NKV) * CH_ROW;           // 51,840
constexpr int Q16   = M * CH_ROW;                      // 102,400
constexpr int BUILD_TOTAL = KV16 + PAD16 + Q16;        // 3,706,880

__global__ __launch_bounds__(256) void build_all_kernel() {
    int idx = blockIdx.x * blockDim.x + threadIdx.x;
    const uint4* z2t = reinterpret_cast<const uint4*>(g_z2t);
    const uint4* z1t = reinterpret_cast<const uint4*>(g_z1t);
    uint4* kv = reinterpret_cast<uint4*>(g_kv);
    uint4* q  = reinterpret_cast<uint4*>(g_q);
    if (idx < KV16) {
        int n  = idx / CH_ROW;
        int f  = idx - n * CH_ROW;
        int h  = n / WK;
        int w  = n - h * WK;
        int ij = f >> 4;
        int cp = f & 15;
        int i  = ij >> 2;
        int j  = ij & 3;
        kv[(size_t)n * CH_ROW + f] = z2t[((h + i) * W + w + j) * 16 + cp];
    } else if (idx < KV16 + PAD16) {
        int p = idx - KV16;
        kv[(size_t)NKV * CH_ROW + p] = make_uint4(0u, 0u, 0u, 0u);
    } else if (idx < BUILD_TOTAL) {
        int p  = idx - KV16 - PAD16;
        int m  = p / CH_ROW;
        int f  = p - m * CH_ROW;
        int ih = m >> 4;
        int iw = m & 15;
        int ij = f >> 4;
        int cp = f & 15;
        int i  = ij >> 2;
        int j  = ij & 3;
        q[(size_t)m * CH_ROW + f] = z1t[((ih * KH + i) * W + iw * KW + j) * 16 + cp];
    }
}

// -------- GEMM tiling: CTA 32(M) x 64(N), 64 threads = 2 warps (32x32 each) ----
constexpr int BM  = 32;
constexpr int BN  = 64;
constexpr int BK  = 64;
constexpr int LDS = 72;
constexpr int STAGES = 4;
constexpr int A_HALVES = BM * LDS;               // 2304
constexpr int B_HALVES = BN * LDS;               // 4608
constexpr int STAGE_HALVES = A_HALVES + B_HALVES;
constexpr int SMEM_BYTES = STAGES * STAGE_HALVES * 2;   // 55296

// ------ kernel 2: attn_unnorm = exp(q @ kv^T / D) + fused row partial sums ------
__global__ __launch_bounds__(64, 4) void gemm_qk_kernel() {
    extern __shared__ __align__(16) __half sm[];
    __shared__ float rsm[2][32];
    const int n0   = blockIdx.x * BN;
    const int m0   = blockIdx.y * BM;
    const int tid  = threadIdx.x;
    const int wn   = tid >> 5, lane = tid & 31;
    constexpr int KT = D / BK;                   // 80

    auto load_stage = [&](int s, int kt) {
        const int k0 = kt * BK;
        __half* As = sm + s * STAGE_HALVES;
        __half* Bs = As + A_HALVES;
#pragma unroll
        for (int i = 0; i < 4; i++) {
            int t = tid + i * 64;
            int r = t >> 3, c8 = (t & 7) << 3;
            cpasync16_ca(smem_u32(&As[r * LDS + c8]),
                         &g_q[(m0 + r) * D + k0 + c8]);
        }
#pragma unroll
        for (int i = 0; i < 8; i++) {
            int t = tid + i * 64;
            int r = t >> 3, c8 = (t & 7) << 3;
            cpasync16(smem_u32(&Bs[r * LDS + c8]),
                      &g_kv[(size_t)(n0 + r) * D + k0 + c8]);
        }
    };

#pragma unroll
    for (int s = 0; s < STAGES - 1; s++) { load_stage(s, s); CP_COMMIT(); }

    float acc[2][4][4] = {};
    uint32_t a[2][2][4], b[2][4][2];

    auto load_frags = [&](const __half* As, const __half* Bs, int ks, int buf) {
#pragma unroll
        for (int mi = 0; mi < 2; mi++) {
            int r = mi * 16 + (lane & 15);
            int c = ks * 16 + (lane >> 4) * 8;
            ldsm_x4(a[buf][mi][0], a[buf][mi][1], a[buf][mi][2], a[buf][mi][3],
                    smem_u32(&As[r * LDS + c]));
        }
#pragma unroll
        for (int nb = 0; nb < 2; nb++) {
            int r = wn * 32 + nb * 16 + (lane & 7) + (lane >> 4) * 8;
            int c = ks * 16 + ((lane >> 3) & 1) * 8;
            uint32_t r0, r1, r2, r3;
            ldsm_x4(r0, r1, r2, r3, smem_u32(&Bs[r * LDS + c]));
            b[buf][nb * 2][0] = r0; b[buf][nb * 2][1] = r1;
            b[buf][nb * 2 + 1][0] = r2; b[buf][nb * 2 + 1][1] = r3;
        }
    };

    for (int kt = 0; kt < KT; kt++) {
        CP_WAIT(STAGES - 2);
        __syncthreads();
        int nxt = kt + STAGES - 1;
        if (nxt < KT) load_stage(nxt & (STAGES - 1), nxt);
        CP_COMMIT();

        const __half* As = sm + (kt & (STAGES - 1)) * STAGE_HALVES;
        const __half* Bs = As + A_HALVES;
        load_frags(As, Bs, 0, 0);
#pragma unroll
        for (int ks = 0; ks < BK / 16; ks++) {
            const int cur = ks & 1;
            if (ks < BK / 16 - 1) load_frags(As, Bs, ks + 1, cur ^ 1);
#pragma unroll
            for (int mi = 0; mi < 2; mi++)
#pragma unroll
                for (int ni = 0; ni < 4; ni++)
                    mma16816(acc[mi][ni], a[cur][mi], b[cur][ni]);
        }
    }

    const float scale = 1.0f / (float)D;
    float rp[2][2] = {};
#pragma unroll
    for (int mi = 0; mi < 2; mi++)
#pragma unroll
        for (int ni = 0; ni < 4; ni++) {
            int row = m0 + mi * 16 + (lane >> 2);
            int col = n0 + wn * 32 + ni * 8 + ((lane & 3) << 1);
            float p00 = (col     < NKV) ? __expf(acc[mi][ni][0] * scale) : 0.f;
            float p01 = (col + 1 < NKV) ? __expf(acc[mi][ni][1] * scale) : 0.f;
            float p10 = (col     < NKV) ? __expf(acc[mi][ni][2] * scale) : 0.f;
            float p11 = (col + 1 < NKV) ? __expf(acc[mi][ni][3] * scale) : 0.f;
            *reinterpret_cast<__half2*>(&g_attn[row * NPAD + col]) =
                __floats2half2_rn(p00, p01);
            *reinterpret_cast<__half2*>(&g_attn[(row + 8) * NPAD + col]) =
                __floats2half2_rn(p10, p11);
            rp[mi][0] += p00 + p01;
            rp[mi][1] += p10 + p11;
        }
#pragma unroll
    for (int o = 1; o < 4; o <<= 1) {
#pragma unroll
        for (int mi = 0; mi < 2; mi++) {
            rp[mi][0] += __shfl_xor_sync(0xffffffffu, rp[mi][0], o);
            rp[mi][1] += __shfl_xor_sync(0xffffffffu, rp[mi][1], o);
        }
    }
    if ((lane & 3) == 0) {
        int r = lane >> 2;
#pragma unroll
        for (int mi = 0; mi < 2; mi++) {
            rsm[wn][mi * 16 + r]     = rp[mi][0];
            rsm[wn][mi * 16 + 8 + r] = rp[mi][1];
        }
    }
    __syncthreads();
    if (tid < 32)
        g_rsum2[m0 + tid][blockIdx.x] = rsm[0][tid] + rsm[1][tid];
}

// ------ kernel 3: out partials = attn_unnorm @ kv (split-K = 2) ------
__global__ __launch_bounds__(64, 4) void gemm_av_kernel() {
    extern __shared__ __align__(16) __half sm[];
    const int n0    = blockIdx.x * BN;           // over D
    const int m0    = blockIdx.y * BM;
    const int split = blockIdx.z;                // 0 or 1
    const int tid   = threadIdx.x;
    const int wn    = tid >> 5, lane = tid & 31;
    constexpr int KT = (NPAD / BK) / 2;          // 44
    const int kbase = split * KT;

    auto load_stage = [&](int s, int kt) {
        const int k0 = (kbase + kt) * BK;
        __half* As = sm + s * STAGE_HALVES;
        __half* Bs = As + A_HALVES;
#pragma unroll
        for (int i = 0; i < 4; i++) {
            int t = tid + i * 64;
            int r = t >> 3, c8 = (t & 7) << 3;
            cpasync16_ca(smem_u32(&As[r * LDS + c8]),
                         &g_attn[(m0 + r) * NPAD + k0 + c8]);
        }
#pragma unroll
        for (int i = 0; i < 8; i++) {
            int t = tid + i * 64;
            int r = t >> 3, c8 = (t & 7) << 3;
            cpasync16(smem_u32(&Bs[r * LDS + c8]),
                      &g_kv[(size_t)(k0 + r) * D + n0 + c8]);
        }
    };

#pragma unroll
    for (int s = 0; s < STAGES - 1; s++) { load_stage(s, s); CP_COMMIT(); }

    float acc[2][4][4] = {};
    uint32_t a[2][2][4], b[2][4][2];

    auto load_frags = [&](const __half* As, const __half* Bs, int ks, int buf) {
#pragma unroll
        for (int mi = 0; mi < 2; mi++) {
            int r = mi * 16 + (lane & 15);
            int c = ks * 16 + (lane >> 4) * 8;
            ldsm_x4(a[buf][mi][0], a[buf][mi][1], a[buf][mi][2], a[buf][mi][3],
                    smem_u32(&As[r * LDS + c]));
        }
#pragma unroll
        for (int nb = 0; nb < 2; nb++) {
            int r = ks * 16 + (lane & 7) + ((lane >> 3) & 1) * 8;
            int c = wn * 32 + nb * 16 + (lane >> 4) * 8;
            uint32_t r0, r1, r2, r3;
            ldsm_x4_t(r0, r1, r2, r3, smem_u32(&Bs[r * LDS + c]));
            b[buf][nb * 2][0] = r0; b[buf][nb * 2][1] = r1;
            b[buf][nb * 2 + 1][0] = r2; b[buf][nb * 2 + 1][1] = r3;
        }
    };

    for (int kt = 0; kt < KT; kt++) {
        CP_WAIT(STAGES - 2);
        __syncthreads();
        int nxt = kt + STAGES - 1;
        if (nxt < KT) load_stage(nxt & (STAGES - 1), nxt);
        CP_COMMIT();

        const __half* As = sm + (kt & (STAGES - 1)) * STAGE_HALVES;
        const __half* Bs = As + A_HALVES;
        load_frags(As, Bs, 0, 0);
#pragma unroll
        for (int ks = 0; ks < BK / 16; ks++) {
            const int cur = ks & 1;
            if (ks < BK / 16 - 1) load_frags(As, Bs, ks + 1, cur ^ 1);
#pragma unroll
            for (int mi = 0; mi < 2; mi++)
#pragma unroll
                for (int ni = 0; ni < 4; ni++)
                    mma16816(acc[mi][ni], a[cur][mi], b[cur][ni]);
        }
    }

    float* op = g_outp[split];
#pragma unroll
    for (int mi = 0; mi < 2; mi++)
#pragma unroll
        for (int ni = 0; ni < 4; ni++) {
            int row = m0 + mi * 16 + (lane >> 2);
            int col = n0 + wn * 32 + ni * 8 + ((lane & 3) << 1);
            *reinterpret_cast<float2*>(&op[(size_t)row * D + col]) =
                make_float2(acc[mi][ni][0], acc[mi][ni][1]);
            *reinterpret_cast<float2*>(&op[(size_t)(row + 8) * D + col]) =
                make_float2(acc[mi][ni][2], acc[mi][ni][3]);
        }
}

// ------ kernel 4: out = (p0 + p1) * inv[m], remapped store ------
__global__ __launch_bounds__(256) void reduce_out_kernel(float* __restrict__ out) {
    __shared__ float sinv;
    const int m  = blockIdx.y;
    const int d0 = blockIdx.x * 512;
    const int tid = threadIdx.x;
    if (tid == 0) {
        float s = 0.f;
#pragma unroll 8
        for (int t = 0; t < NT1; t++) s += g_rsum2[m][t];
        sinv = 1.0f / s;
    }
    __syncthreads();
    const float inv = sinv;
    const int d = d0 + tid * 2;
    const float2 p0 = *reinterpret_cast<const float2*>(&g_outp[0][(size_t)m * D + d]);
    const float2 p1 = *reinterpret_cast<const float2*>(&g_outp[1][(size_t)m * D + d]);
    const float v0 = (p0.x + p1.x) * inv;
    const float v1 = (p0.y + p1.y) * inv;
    // decode d = ij*128 + c ; two consecutive d share ij, c and c+1
    const int ij = d >> 7;
    const int c  = d & 127;
    const int i  = ij >> 2;
    const int j  = ij & 3;
    const int ih = m >> 4;
    const int iw = m & 15;
    const int base = (ih * KH + i) * W + iw * KW + j;
    out[(c * H) * W + base + 0 * 0] = v0;         // c
    out[((c + 1) * H) * W + base]   = v1;         // c+1
}

// ---------------- launch ----------------
extern "C" void kernel_launch(void* const* d_in, const int* in_sizes, int n_in,
                              void* d_out, int out_size) {
    const float* z1 = (const float*)d_in[0];
    const float* z2 = (const float*)d_in[1];
    float* out = (float*)d_out;

    cudaFuncSetAttribute(gemm_qk_kernel,
                         cudaFuncAttributeMaxDynamicSharedMemorySize, SMEM_BYTES);
    cudaFuncSetAttribute(gemm_av_kernel,
                         cudaFuncAttributeMaxDynamicSharedMemorySize, SMEM_BYTES);

    transpose_kernel<<<dim3(HW / 32, KC / 32, 2), 256>>>(z1, z2);
    build_all_kernel<<<(BUILD_TOTAL + 255) / 256, 256>>>();
    gemm_qk_kernel<<<dim3(NPAD / BN, M / BM), 64, SMEM_BYTES>>>();      // 88x5 = 440
    gemm_av_kernel<<<dim3(D / BN, M / BM, 2), 64, SMEM_BYTES>>>();      // 80x5x2 = 800
    reduce_out_kernel<<<dim3(D / 512, M), 256>>>(out);                  // 10x160
}

// round 15
// speedup vs baseline: 1.0874x; 1.0874x over previous
#include <cuda_runtime.h>
#include <cuda_fp16.h>
#include <cstdint>

// ---------------- problem constants ----------------
constexpr int KC = 128, KH = 10, KW = 4;
constexpr int H = 100, W = 64;
constexpr int HW = H * W;                  // 6400
constexpr int NH = 10, NW = 16;
constexpr int M = NH * NW;                 // 160 q rows
constexpr int MPAD = 192;                  // 3 tiles of 64
constexpr int HK = H - KH + 1;             // 91
constexpr int WK = W - KW + 1;             // 61
constexpr int NKV = HK * WK;               // 5551
constexpr int NPAD = 5632;                 // 88*64
constexpr int D = KC * KH * KW;            // 5120
constexpr int NT1 = NPAD / 64;             // 88 qk n-tiles

// Feature ordering: d = (i*4+j)*128 + c   (ij-major, channel-fast)

// ---------------- scratch ----------------
__device__ __half g_z1t[(size_t)HW * KC];      // [hw][c] channel-fast
__device__ __half g_z2t[(size_t)HW * KC];
__device__ __half g_kv[(size_t)NPAD * D];      // [n][d]
__device__ __half g_q[(size_t)MPAD * D];       // rows 160..191 zeroed by build
__device__ __half g_attn[(size_t)MPAD * NPAD]; // rows 160..191 = exp(0)=1, unused
__device__ float  g_rsum2[M][NT1];             // per-(row, n-tile) partial sums

// ---------------- ptx helpers ----------------
__device__ __forceinline__ uint32_t smem_u32(const void* p) {
    return (uint32_t)__cvta_generic_to_shared(p);
}
__device__ __forceinline__ void ldsm_x4(uint32_t& r0, uint32_t& r1, uint32_t& r2,
                                        uint32_t& r3, uint32_t a) {
    asm volatile("ldmatrix.sync.aligned.m8n8.x4.shared.b16 {%0,%1,%2,%3}, [%4];"
                 : "=r"(r0), "=r"(r1), "=r"(r2), "=r"(r3) : "r"(a));
}
__device__ __forceinline__ void ldsm_x4_t(uint32_t& r0, uint32_t& r1, uint32_t& r2,
                                          uint32_t& r3, uint32_t a) {
    asm volatile("ldmatrix.sync.aligned.m8n8.x4.trans.shared.b16 {%0,%1,%2,%3}, [%4];"
                 : "=r"(r0), "=r"(r1), "=r"(r2), "=r"(r3) : "r"(a));
}
__device__ __forceinline__ void mma16816(float* c, const uint32_t* a, const uint32_t* b) {
    asm volatile("mma.sync.aligned.m16n8k16.row.col.f32.f16.f16.f32 "
                 "{%0,%1,%2,%3}, {%4,%5,%6,%7}, {%8,%9}, {%0,%1,%2,%3};"
                 : "+f"(c[0]), "+f"(c[1]), "+f"(c[2]), "+f"(c[3])
                 : "r"(a[0]), "r"(a[1]), "r"(a[2]), "r"(a[3]),
                   "r"(b[0]), "r"(b[1]));
}
__device__ __forceinline__ void cpasync16(uint32_t s, const void* g) {
    asm volatile("cp.async.cg.shared.global [%0], [%1], 16;" :: "r"(s), "l"(g));
}
__device__ __forceinline__ void cpasync16_ca(uint32_t s, const void* g) {
    asm volatile("cp.async.ca.shared.global [%0], [%1], 16;" :: "r"(s), "l"(g));
}
#define CP_COMMIT() asm volatile("cp.async.commit_group;")
#define CP_WAIT(n)  asm volatile("cp.async.wait_group %0;" :: "n"(n))

// ------- kernel 0: transpose z1/z2 [c][hw] f32 -> [hw][c] f16 -------
__global__ __launch_bounds__(256) void transpose_kernel(const float* __restrict__ z1,
                                                        const float* __restrict__ z2) {
    __shared__ float tile[32][33];
    const float* src = blockIdx.z ? z2 : z1;
    __half* dst      = blockIdx.z ? g_z2t : g_z1t;
    const int hw0 = blockIdx.x * 32;
    const int c0  = blockIdx.y * 32;
    const int tx = threadIdx.x & 31;
    const int ty = threadIdx.x >> 5;               // 0..7
#pragma unroll
    for (int k = 0; k < 4; k++)
        tile[ty + 8 * k][tx] = src[(size_t)(c0 + ty + 8 * k) * HW + hw0 + tx];
    __syncthreads();
#pragma unroll
    for (int k = 0; k < 4; k++)
        dst[(size_t)(hw0 + ty + 8 * k) * KC + c0 + tx] =
            __float2half(tile[tx][ty + 8 * k]);
}

// ------- kernel 1: build q + kv, fully coalesced 16B chunks -------
constexpr int CH_ROW = D / 8;                          // 640 chunks per row
constexpr int KV16   = NKV * CH_ROW;                   // 3,552,640
constexpr int PAD16  = (NPAD - NKV) * CH_ROW;          // 51,840
constexpr int Q16    = M * CH_ROW;                     // 102,400
constexpr int QPAD16 = (MPAD - M) * CH_ROW;            // 20,480
constexpr int BUILD_TOTAL = KV16 + PAD16 + Q16 + QPAD16;

__global__ __launch_bounds__(256) void build_all_kernel() {
    int idx = blockIdx.x * blockDim.x + threadIdx.x;
    const uint4* z2t = reinterpret_cast<const uint4*>(g_z2t);
    const uint4* z1t = reinterpret_cast<const uint4*>(g_z1t);
    uint4* kv = reinterpret_cast<uint4*>(g_kv);
    uint4* q  = reinterpret_cast<uint4*>(g_q);
    if (idx < KV16) {
        int n  = idx / CH_ROW;
        int f  = idx - n * CH_ROW;
        int h  = n / WK;
        int w  = n - h * WK;
        int ij = f >> 4;
        int cp = f & 15;
        int i  = ij >> 2;
        int j  = ij & 3;
        kv[(size_t)n * CH_ROW + f] = z2t[((h + i) * W + w + j) * 16 + cp];
    } else if (idx < KV16 + PAD16) {
        int p = idx - KV16;
        kv[(size_t)NKV * CH_ROW + p] = make_uint4(0u, 0u, 0u, 0u);
    } else if (idx < KV16 + PAD16 + Q16) {
        int p  = idx - KV16 - PAD16;
        int m  = p / CH_ROW;
        int f  = p - m * CH_ROW;
        int ih = m >> 4;
        int iw = m & 15;
        int ij = f >> 4;
        int cp = f & 15;
        int i  = ij >> 2;
        int j  = ij & 3;
        q[(size_t)m * CH_ROW + f] = z1t[((ih * KH + i) * W + iw * KW + j) * 16 + cp];
    } else if (idx < BUILD_TOTAL) {
        int p = idx - KV16 - PAD16 - Q16;
        q[(size_t)M * CH_ROW + p] = make_uint4(0u, 0u, 0u, 0u);
    }
}

// -- GEMM tiling: CTA 64(M) x 64(N), 128 threads = 4 warps 2x2 (32x32 each) --
constexpr int BM  = 64;
constexpr int BN  = 64;
constexpr int BK  = 64;
constexpr int LDS = 72;
constexpr int STAGES = 4;
constexpr int A_HALVES = BM * LDS;               // 4608
constexpr int B_HALVES = BN * LDS;               // 4608
constexpr int STAGE_HALVES = A_HALVES + B_HALVES;
constexpr int SMEM_BYTES = STAGES * STAGE_HALVES * 2;   // 73728 -> occ 3

// ------ kernel 2: attn_unnorm = exp(q @ kv^T / D) + fused row partial sums ------
__global__ __launch_bounds__(128, 3) void gemm_qk_kernel() {
    extern __shared__ __align__(16) __half sm[];
    __shared__ float rsm[2][64];
    const int n0   = blockIdx.x * BN;
    const int m0   = blockIdx.y * BM;
    const int tid  = threadIdx.x;
    const int warp = tid >> 5, lane = tid & 31;
    const int wm = warp >> 1, wn = warp & 1;
    constexpr int KT = D / BK;                   // 80

    auto load_stage = [&](int s, int kt) {
        const int k0 = kt * BK;
        __half* As = sm + s * STAGE_HALVES;
        __half* Bs = As + A_HALVES;
#pragma unroll
        for (int i = 0; i < 4; i++) {            // A: 512 chunks / 128 thr
            int t = tid + i * 128;
            int r = t >> 3, c8 = (t & 7) << 3;
            cpasync16_ca(smem_u32(&As[r * LDS + c8]),
                         &g_q[(size_t)(m0 + r) * D + k0 + c8]);
        }
#pragma unroll
        for (int i = 0; i < 4; i++) {            // B: 512 chunks
            int t = tid + i * 128;
            int r = t >> 3, c8 = (t & 7) << 3;
            cpasync16(smem_u32(&Bs[r * LDS + c8]),
                      &g_kv[(size_t)(n0 + r) * D + k0 + c8]);
        }
    };

#pragma unroll
    for (int s = 0; s < STAGES - 1; s++) { load_stage(s, s); CP_COMMIT(); }

    float acc[2][4][4] = {};
    uint32_t a[2][2][4], b[2][4][2];

    auto load_frags = [&](const __half* As, const __half* Bs, int ks, int buf) {
#pragma unroll
        for (int mi = 0; mi < 2; mi++) {
            int r = wm * 32 + mi * 16 + (lane & 15);
            int c = ks * 16 + (lane >> 4) * 8;
            ldsm_x4(a[buf][mi][0], a[buf][mi][1], a[buf][mi][2], a[buf][mi][3],
                    smem_u32(&As[r * LDS + c]));
        }
#pragma unroll
        for (int nb = 0; nb < 2; nb++) {
            int r = wn * 32 + nb * 16 + (lane & 7) + (lane >> 4) * 8;
            int c = ks * 16 + ((lane >> 3) & 1) * 8;
            uint32_t r0, r1, r2, r3;
            ldsm_x4(r0, r1, r2, r3, smem_u32(&Bs[r * LDS + c]));
            b[buf][nb * 2][0] = r0; b[buf][nb * 2][1] = r1;
            b[buf][nb * 2 + 1][0] = r2; b[buf][nb * 2 + 1][1] = r3;
        }
    };

    for (int kt = 0; kt < KT; kt++) {
        CP_WAIT(STAGES - 2);
        __syncthreads();
        int nxt = kt + STAGES - 1;
        if (nxt < KT) load_stage(nxt & (STAGES - 1), nxt);
        CP_COMMIT();

        const __half* As = sm + (kt & (STAGES - 1)) * STAGE_HALVES;
        const __half* Bs = As + A_HALVES;
        load_frags(As, Bs, 0, 0);
#pragma unroll
        for (int ks = 0; ks < BK / 16; ks++) {
            const int cur = ks & 1;
            if (ks < BK / 16 - 1) load_frags(As, Bs, ks + 1, cur ^ 1);
#pragma unroll
            for (int mi = 0; mi < 2; mi++)
#pragma unroll
                for (int ni = 0; ni < 4; ni++)
                    mma16816(acc[mi][ni], a[cur][mi], b[cur][ni]);
        }
    }

    const float scale = 1.0f / (float)D;
    float rp[2][2] = {};
#pragma unroll
    for (int mi = 0; mi < 2; mi++)
#pragma unroll
        for (int ni = 0; ni < 4; ni++) {
            int row = m0 + wm * 32 + mi * 16 + (lane >> 2);
            int col = n0 + wn * 32 + ni * 8 + ((lane & 3) << 1);
            float p00 = (col     < NKV) ? __expf(acc[mi][ni][0] * scale) : 0.f;
            float p01 = (col + 1 < NKV) ? __expf(acc[mi][ni][1] * scale) : 0.f;
            float p10 = (col     < NKV) ? __expf(acc[mi][ni][2] * scale) : 0.f;
            float p11 = (col + 1 < NKV) ? __expf(acc[mi][ni][3] * scale) : 0.f;
            *reinterpret_cast<__half2*>(&g_attn[(size_t)row * NPAD + col]) =
                __floats2half2_rn(p00, p01);
            *reinterpret_cast<__half2*>(&g_attn[(size_t)(row + 8) * NPAD + col]) =
                __floats2half2_rn(p10, p11);
            rp[mi][0] += p00 + p01;
            rp[mi][1] += p10 + p11;
        }
#pragma unroll
    for (int o = 1; o < 4; o <<= 1) {
#pragma unroll
        for (int mi = 0; mi < 2; mi++) {
            rp[mi][0] += __shfl_xor_sync(0xffffffffu, rp[mi][0], o);
            rp[mi][1] += __shfl_xor_sync(0xffffffffu, rp[mi][1], o);
        }
    }
    if ((lane & 3) == 0) {
        int r = lane >> 2;
#pragma unroll
        for (int mi = 0; mi < 2; mi++) {
            rsm[wn][wm * 32 + mi * 16 + r]     = rp[mi][0];
            rsm[wn][wm * 32 + mi * 16 + 8 + r] = rp[mi][1];
        }
    }
    __syncthreads();
    if (tid < 64 && m0 + tid < M)
        g_rsum2[m0 + tid][blockIdx.x] = rsm[0][tid] + rsm[1][tid];
}

// ---------------- kernel 3: out = (attn_unnorm @ kv) * inv[row] ----------------
// feature decode for d = ij*128 + c
__device__ __forceinline__ void store_out(float* __restrict__ out, int m, int d, float v) {
    if (m >= M) return;
    int ij = d >> 7;
    int c  = d & 127;
    int i  = ij >> 2;
    int j  = ij & 3;
    int ih = m >> 4;
    int iw = m & 15;
    out[(c * H + ih * KH + i) * W + iw * KW + j] = v;
}

__global__ __launch_bounds__(128, 3) void gemm_av_kernel(float* __restrict__ out) {
    extern __shared__ __align__(16) __half sm[];
    __shared__ float invs[64];
    const int n0   = blockIdx.x * BN;            // over D
    const int m0   = blockIdx.y * BM;
    const int tid  = threadIdx.x;
    const int warp = tid >> 5, lane = tid & 31;
    const int wm = warp >> 1, wn = warp & 1;
    constexpr int KT = NPAD / BK;                // 88

    if (tid < 64) {
        float v = 1.0f;
        if (m0 + tid < M) {
            float s = 0.f;
#pragma unroll 8
            for (int t = 0; t < NT1; t++) s += g_rsum2[m0 + tid][t];
            v = 1.0f / s;
        }
        invs[tid] = v;
    }

    auto load_stage = [&](int s, int kt) {
        const int k0 = kt * BK;
        __half* As = sm + s * STAGE_HALVES;
        __half* Bs = As + A_HALVES;
#pragma unroll
        for (int i = 0; i < 4; i++) {            // A: attn rows (k-contig)
            int t = tid + i * 128;
            int r = t >> 3, c8 = (t & 7) << 3;
            cpasync16_ca(smem_u32(&As[r * LDS + c8]),
                         &g_attn[(size_t)(m0 + r) * NPAD + k0 + c8]);
        }
#pragma unroll
        for (int i = 0; i < 4; i++) {            // B: 64 k-rows x 8 chunks (n-contig)
            int t = tid + i * 128;
            int r = t >> 3, c8 = (t & 7) << 3;
            cpasync16(smem_u32(&Bs[r * LDS + c8]),
                      &g_kv[(size_t)(k0 + r) * D + n0 + c8]);
        }
    };

#pragma unroll
    for (int s = 0; s < STAGES - 1; s++) { load_stage(s, s); CP_COMMIT(); }

    float acc[2][4][4] = {};
    uint32_t a[2][2][4], b[2][4][2];

    auto load_frags = [&](const __half* As, const __half* Bs, int ks, int buf) {
#pragma unroll
        for (int mi = 0; mi < 2; mi++) {
            int r = wm * 32 + mi * 16 + (lane & 15);
            int c = ks * 16 + (lane >> 4) * 8;
            ldsm_x4(a[buf][mi][0], a[buf][mi][1], a[buf][mi][2], a[buf][mi][3],
                    smem_u32(&As[r * LDS + c]));
        }
#pragma unroll
        for (int nb = 0; nb < 2; nb++) {
            int r = ks * 16 + (lane & 7) + ((lane >> 3) & 1) * 8;
            int c = wn * 32 + nb * 16 + (lane >> 4) * 8;
            uint32_t r0, r1, r2, r3;
            ldsm_x4_t(r0, r1, r2, r3, smem_u32(&Bs[r * LDS + c]));
            b[buf][nb * 2][0] = r0; b[buf][nb * 2][1] = r1;
            b[buf][nb * 2 + 1][0] = r2; b[buf][nb * 2 + 1][1] = r3;
        }
    };

    for (int kt = 0; kt < KT; kt++) {
        CP_WAIT(STAGES - 2);
        __syncthreads();
        int nxt = kt + STAGES - 1;
        if (nxt < KT) load_stage(nxt & (STAGES - 1), nxt);
        CP_COMMIT();

        const __half* As = sm + (kt & (STAGES - 1)) * STAGE_HALVES;
        const __half* Bs = As + A_HALVES;
        load_frags(As, Bs, 0, 0);
#pragma unroll
        for (int ks = 0; ks < BK / 16; ks++) {
            const int cur = ks & 1;
            if (ks < BK / 16 - 1) load_frags(As, Bs, ks + 1, cur ^ 1);
#pragma unroll
            for (int mi = 0; mi < 2; mi++)
#pragma unroll
                for (int ni = 0; ni < 4; ni++)
                    mma16816(acc[mi][ni], a[cur][mi], b[cur][ni]);
        }
    }

#pragma unroll
    for (int mi = 0; mi < 2; mi++) {
        int row = m0 + wm * 32 + mi * 16 + (lane >> 2);
        const float inv0 = invs[wm * 32 + mi * 16 + (lane >> 2)];
        const float inv1 = invs[wm * 32 + mi * 16 + 8 + (lane >> 2)];
#pragma unroll
        for (int ni = 0; ni < 4; ni++) {
            int col = n0 + wn * 32 + ni * 8 + ((lane & 3) << 1);
            store_out(out, row,     col,     acc[mi][ni][0] * inv0);
            store_out(out, row,     col + 1, acc[mi][ni][1] * inv0);
            store_out(out, row + 8, col,     acc[mi][ni][2] * inv1);
            store_out(out, row + 8, col + 1, acc[mi][ni][3] * inv1);
        }
    }
}

// ---------------- launch ----------------
extern "C" void kernel_launch(void* const* d_in, const int* in_sizes, int n_in,
                              void* d_out, int out_size) {
    const float* z1 = (const float*)d_in[0];
    const float* z2 = (const float*)d_in[1];
    float* out = (float*)d_out;

    cudaFuncSetAttribute(gemm_qk_kernel,
                         cudaFuncAttributeMaxDynamicSharedMemorySize, SMEM_BYTES);
    cudaFuncSetAttribute(gemm_av_kernel,
                         cudaFuncAttributeMaxDynamicSharedMemorySize, SMEM_BYTES);

    transpose_kernel<<<dim3(HW / 32, KC / 32, 2), 256>>>(z1, z2);
    build_all_kernel<<<(BUILD_TOTAL + 255) / 256, 256>>>();
    gemm_qk_kernel<<<dim3(NPAD / BN, MPAD / BM), 128, SMEM_BYTES>>>();  // 88x3 = 264
    gemm_av_kernel<<<dim3(D / BN, MPAD / BM), 128, SMEM_BYTES>>>(out);  // 80x3 = 240
}

// round 16
// speedup vs baseline: 1.2032x; 1.1064x over previous
#include <cuda_runtime.h>
#include <cuda_fp16.h>
#include <cstdint>

// ---------------- problem constants ----------------
constexpr int KC = 128, KH = 10, KW = 4;
constexpr int H = 100, W = 64;
constexpr int HW = H * W;                  // 6400
constexpr int NH = 10, NW = 16;
constexpr int M = NH * NW;                 // 160 q rows
constexpr int HK = H - KH + 1;             // 91
constexpr int WK = W - KW + 1;             // 61
constexpr int NKV = HK * WK;               // 5551
constexpr int NPAD = 5632;                 // 88*64
constexpr int D = KC * KH * KW;            // 5120
constexpr int NT1 = NPAD / 64;             // 88 qk n-tiles

// Feature ordering: d = (i*4+j)*128 + c   (ij-major, channel-fast)
// kv[n][d] == z2t[base(n) + ijoff(ij)][c],  base(n) = (n/61)*64 + n%61,
// ijoff = (ij>>2)*64 + (ij&3).  No materialized kv/q needed.

// ---------------- scratch (total ~5 MB: all L2-hot) ----------------
__device__ __half g_z1t[(size_t)HW * KC];      // [hw][c] channel-fast (1.6 MB)
__device__ __half g_z2t[(size_t)HW * KC];      // (1.6 MB)
__device__ __half g_attn[(size_t)M * NPAD];    // unnormalized exp(scores) (1.8 MB)
__device__ float  g_rsum2[M][NT1];             // per-(row, n-tile) partial sums

// ---------------- ptx helpers ----------------
__device__ __forceinline__ uint32_t smem_u32(const void* p) {
    return (uint32_t)__cvta_generic_to_shared(p);
}
__device__ __forceinline__ void ldsm_x4(uint32_t& r0, uint32_t& r1, uint32_t& r2,
                                        uint32_t& r3, uint32_t a) {
    asm volatile("ldmatrix.sync.aligned.m8n8.x4.shared.b16 {%0,%1,%2,%3}, [%4];"
                 : "=r"(r0), "=r"(r1), "=r"(r2), "=r"(r3) : "r"(a));
}
__device__ __forceinline__ void ldsm_x4_t(uint32_t& r0, uint32_t& r1, uint32_t& r2,
                                          uint32_t& r3, uint32_t a) {
    asm volatile("ldmatrix.sync.aligned.m8n8.x4.trans.shared.b16 {%0,%1,%2,%3}, [%4];"
                 : "=r"(r0), "=r"(r1), "=r"(r2), "=r"(r3) : "r"(a));
}
__device__ __forceinline__ void mma16816(float* c, const uint32_t* a, const uint32_t* b) {
    asm volatile("mma.sync.aligned.m16n8k16.row.col.f32.f16.f16.f32 "
                 "{%0,%1,%2,%3}, {%4,%5,%6,%7}, {%8,%9}, {%0,%1,%2,%3};"
                 : "+f"(c[0]), "+f"(c[1]), "+f"(c[2]), "+f"(c[3])
                 : "r"(a[0]), "r"(a[1]), "r"(a[2]), "r"(a[3]),
                   "r"(b[0]), "r"(b[1]));
}
__device__ __forceinline__ void cpasync16_ca(uint32_t s, const void* g) {
    asm volatile("cp.async.ca.shared.global [%0], [%1], 16;" :: "r"(s), "l"(g));
}
#define CP_COMMIT() asm volatile("cp.async.commit_group;")
#define CP_WAIT(n)  asm volatile("cp.async.wait_group %0;" :: "n"(n))

// base(n) for kv row n (clamped for pad rows; garbage * attn(=0) stays finite)
__device__ __forceinline__ int kv_base(int n) {
    if (n >= NKV) return 0;
    int h = n / WK;
    int w = n - h * WK;
    return h * W + w;
}

// ------- kernel 0: transpose z1/z2 [c][hw] f32 -> [hw][c] f16 -------
__global__ __launch_bounds__(256) void transpose_kernel(const float* __restrict__ z1,
                                                        const float* __restrict__ z2) {
    __shared__ float tile[32][33];
    const float* src = blockIdx.z ? z2 : z1;
    __half* dst      = blockIdx.z ? g_z2t : g_z1t;
    const int hw0 = blockIdx.x * 32;
    const int c0  = blockIdx.y * 32;
    const int tx = threadIdx.x & 31;
    const int ty = threadIdx.x >> 5;               // 0..7
#pragma unroll
    for (int k = 0; k < 4; k++)
        tile[ty + 8 * k][tx] = src[(size_t)(c0 + ty + 8 * k) * HW + hw0 + tx];
    __syncthreads();
#pragma unroll
    for (int k = 0; k < 4; k++)
        dst[(size_t)(hw0 + ty + 8 * k) * KC + c0 + tx] =
            __float2half(tile[tx][ty + 8 * k]);
}

// -------- GEMM tiling: CTA 32(M) x 64(N), 64 threads = 2 warps (32x32 each) ----
constexpr int BM  = 32;
constexpr int BN  = 64;
constexpr int BK  = 64;
constexpr int LDS = 72;
constexpr int STAGES = 4;
constexpr int A_HALVES = BM * LDS;               // 2304
constexpr int B_HALVES = BN * LDS;               // 4608
constexpr int STAGE_HALVES = A_HALVES + B_HALVES;
constexpr int SMEM_BYTES = STAGES * STAGE_HALVES * 2;   // 55296

// ------ kernel 1: attn_unnorm = exp(q @ kv^T / D) + fused row partial sums ------
// A gathered from z1t, B gathered from z2t (no materialized q/kv).
__global__ __launch_bounds__(64, 4) void gemm_qk_kernel() {
    extern __shared__ __align__(16) __half sm[];
    __shared__ float rsm[2][32];
    const int n0   = blockIdx.x * BN;
    const int m0   = blockIdx.y * BM;
    const int tid  = threadIdx.x;
    const int wn   = tid >> 5, lane = tid & 31;
    constexpr int KT = D / BK;                   // 80
    const int c8 = (tid & 7) << 3;               // fixed per thread

    // per-thread row bases (fixed across kt)
    int baseq[4];
#pragma unroll
    for (int it = 0; it < 4; it++) {
        int m = m0 + (tid >> 3) + it * 8;
        baseq[it] = (m >> 4) * (KH * W) + (m & 15) * KW;     // ih*640 + iw*4
    }
    int baseb[8];
#pragma unroll
    for (int it = 0; it < 8; it++)
        baseb[it] = kv_base(n0 + (tid >> 3) + it * 8);

    auto load_stage = [&](int s, int kt) {
        const int ij    = kt >> 1;
        const int c0    = (kt & 1) << 6;
        const int ijoff = ((ij >> 2) << 6) + (ij & 3);       // i*64 + j
        __half* As = sm + s * STAGE_HALVES;
        __half* Bs = As + A_HALVES;
        const int rA = tid >> 3;
#pragma unroll
        for (int it = 0; it < 4; it++) {
            cpasync16_ca(smem_u32(&As[(rA + it * 8) * LDS + c8]),
                         &g_z1t[(size_t)(baseq[it] + ijoff) * KC + c0 + c8]);
        }
#pragma unroll
        for (int it = 0; it < 8; it++) {
            cpasync16_ca(smem_u32(&Bs[(rA + it * 8) * LDS + c8]),
                         &g_z2t[(size_t)(baseb[it] + ijoff) * KC + c0 + c8]);
        }
    };

#pragma unroll
    for (int s = 0; s < STAGES - 1; s++) { load_stage(s, s); CP_COMMIT(); }

    float acc[2][4][4] = {};
    uint32_t a[2][2][4], b[2][4][2];

    auto load_frags = [&](const __half* As, const __half* Bs, int ks, int buf) {
#pragma unroll
        for (int mi = 0; mi < 2; mi++) {
            int r = mi * 16 + (lane & 15);
            int c = ks * 16 + (lane >> 4) * 8;
            ldsm_x4(a[buf][mi][0], a[buf][mi][1], a[buf][mi][2], a[buf][mi][3],
                    smem_u32(&As[r * LDS + c]));
        }
#pragma unroll
        for (int nb = 0; nb < 2; nb++) {
            int r = wn * 32 + nb * 16 + (lane & 7) + (lane >> 4) * 8;
            int c = ks * 16 + ((lane >> 3) & 1) * 8;
            uint32_t r0, r1, r2, r3;
            ldsm_x4(r0, r1, r2, r3, smem_u32(&Bs[r * LDS + c]));
            b[buf][nb * 2][0] = r0; b[buf][nb * 2][1] = r1;
            b[buf][nb * 2 + 1][0] = r2; b[buf][nb * 2 + 1][1] = r3;
        }
    };

    for (int kt = 0; kt < KT; kt++) {
        CP_WAIT(STAGES - 2);
        __syncthreads();
        int nxt = kt + STAGES - 1;
        if (nxt < KT) load_stage(nxt & (STAGES - 1), nxt);
        CP_COMMIT();

        const __half* As = sm + (kt & (STAGES - 1)) * STAGE_HALVES;
        const __half* Bs = As + A_HALVES;
        load_frags(As, Bs, 0, 0);
#pragma unroll
        for (int ks = 0; ks < BK / 16; ks++) {
            const int cur = ks & 1;
            if (ks < BK / 16 - 1) load_frags(As, Bs, ks + 1, cur ^ 1);
#pragma unroll
            for (int mi = 0; mi < 2; mi++)
#pragma unroll
                for (int ni = 0; ni < 4; ni++)
                    mma16816(acc[mi][ni], a[cur][mi], b[cur][ni]);
        }
    }

    // epilogue: p = exp(s/D) (|s/D| small), mask pad cols, fp16 store + partials
    const float scale = 1.0f / (float)D;
    float rp[2][2] = {};
#pragma unroll
    for (int mi = 0; mi < 2; mi++)
#pragma unroll
        for (int ni = 0; ni < 4; ni++) {
            int row = m0 + mi * 16 + (lane >> 2);
            int col = n0 + wn * 32 + ni * 8 + ((lane & 3) << 1);
            float p00 = (col     < NKV) ? __expf(acc[mi][ni][0] * scale) : 0.f;
            float p01 = (col + 1 < NKV) ? __expf(acc[mi][ni][1] * scale) : 0.f;
            float p10 = (col     < NKV) ? __expf(acc[mi][ni][2] * scale) : 0.f;
            float p11 = (col + 1 < NKV) ? __expf(acc[mi][ni][3] * scale) : 0.f;
            *reinterpret_cast<__half2*>(&g_attn[(size_t)row * NPAD + col]) =
                __floats2half2_rn(p00, p01);
            *reinterpret_cast<__half2*>(&g_attn[(size_t)(row + 8) * NPAD + col]) =
                __floats2half2_rn(p10, p11);
            rp[mi][0] += p00 + p01;
            rp[mi][1] += p10 + p11;
        }
#pragma unroll
    for (int o = 1; o < 4; o <<= 1) {
#pragma unroll
        for (int mi = 0; mi < 2; mi++) {
            rp[mi][0] += __shfl_xor_sync(0xffffffffu, rp[mi][0], o);
            rp[mi][1] += __shfl_xor_sync(0xffffffffu, rp[mi][1], o);
        }
    }
    if ((lane & 3) == 0) {
        int r = lane >> 2;
#pragma unroll
        for (int mi = 0; mi < 2; mi++) {
            rsm[wn][mi * 16 + r]     = rp[mi][0];
            rsm[wn][mi * 16 + 8 + r] = rp[mi][1];
        }
    }
    __syncthreads();
    if (tid < 32)
        g_rsum2[m0 + tid][blockIdx.x] = rsm[0][tid] + rsm[1][tid];
}

// ------ kernel 2: out = (attn_unnorm @ kv) * inv[row] ------
// A from g_attn; B gathered from z2t: tile rows = contraction n, cols = d-chunk.
__device__ __forceinline__ void store_out(float* __restrict__ out, int m, int d, float v) {
    int ij = d >> 7;
    int c  = d & 127;
    int i  = ij >> 2;
    int j  = ij & 3;
    int ih = m >> 4;
    int iw = m & 15;
    out[(c * H + ih * KH + i) * W + iw * KW + j] = v;
}

__global__ __launch_bounds__(64, 4) void gemm_av_kernel(float* __restrict__ out) {
    extern __shared__ __align__(16) __half sm[];
    __shared__ float invs[32];
    const int n0   = blockIdx.x * BN;            // over D
    const int m0   = blockIdx.y * BM;
    const int tid  = threadIdx.x;
    const int wn   = tid >> 5, lane = tid & 31;
    constexpr int KT = NPAD / BK;                // 88
    const int c8 = (tid & 7) << 3;

    // d-chunk constants (fixed per CTA): ij = n0>>7, c0 = n0&127
    const int ij_cta    = n0 >> 7;
    const int c0_cta    = n0 & 127;              // 0 or 64
    const int ijoff_cta = ((ij_cta >> 2) << 6) + (ij_cta & 3);

    if (tid < 32) {
        float s = 0.f;
#pragma unroll 8
        for (int t = 0; t < NT1; t++) s += g_rsum2[m0 + tid][t];
        invs[tid] = 1.0f / s;
    }

    auto load_stage = [&](int s, int kt) {
        const int k0 = kt * BK;
        __half* As = sm + s * STAGE_HALVES;
        __half* Bs = As + A_HALVES;
        const int rA = tid >> 3;
#pragma unroll
        for (int it = 0; it < 4; it++) {         // A: attn rows (k-contig)
            cpasync16_ca(smem_u32(&As[(rA + it * 8) * LDS + c8]),
                         &g_attn[(size_t)(m0 + rA + it * 8) * NPAD + k0 + c8]);
        }
#pragma unroll
        for (int it = 0; it < 8; it++) {         // B: 64 contraction rows from z2t
            int n = k0 + rA + it * 8;
            int base = kv_base(n);
            cpasync16_ca(smem_u32(&Bs[(rA + it * 8) * LDS + c8]),
                         &g_z2t[(size_t)(base + ijoff_cta) * KC + c0_cta + c8]);
        }
    };

#pragma unroll
    for (int s = 0; s < STAGES - 1; s++) { load_stage(s, s); CP_COMMIT(); }

    float acc[2][4][4] = {};
    uint32_t a[2][2][4], b[2][4][2];

    auto load_frags = [&](const __half* As, const __half* Bs, int ks, int buf) {
#pragma unroll
        for (int mi = 0; mi < 2; mi++) {
            int r = mi * 16 + (lane & 15);
            int c = ks * 16 + (lane >> 4) * 8;
            ldsm_x4(a[buf][mi][0], a[buf][mi][1], a[buf][mi][2], a[buf][mi][3],
                    smem_u32(&As[r * LDS + c]));
        }
#pragma unroll
        for (int nb = 0; nb < 2; nb++) {
            int r = ks * 16 + (lane & 7) + ((lane >> 3) & 1) * 8;
            int c = wn * 32 + nb * 16 + (lane >> 4) * 8;
            uint32_t r0, r1, r2, r3;
            ldsm_x4_t(r0, r1, r2, r3, smem_u32(&Bs[r * LDS + c]));
            b[buf][nb * 2][0] = r0; b[buf][nb * 2][1] = r1;
            b[buf][nb * 2 + 1][0] = r2; b[buf][nb * 2 + 1][1] = r3;
        }
    };

    for (int kt = 0; kt < KT; kt++) {
        CP_WAIT(STAGES - 2);
        __syncthreads();
        int nxt = kt + STAGES - 1;
        if (nxt < KT) load_stage(nxt & (STAGES - 1), nxt);
        CP_COMMIT();

        const __half* As = sm + (kt & (STAGES - 1)) * STAGE_HALVES;
        const __half* Bs = As + A_HALVES;
        load_frags(As, Bs, 0, 0);
#pragma unroll
        for (int ks = 0; ks < BK / 16; ks++) {
            const int cur = ks & 1;
            if (ks < BK / 16 - 1) load_frags(As, Bs, ks + 1, cur ^ 1);
#pragma unroll
            for (int mi = 0; mi < 2; mi++)
#pragma unroll
                for (int ni = 0; ni < 4; ni++)
                    mma16816(acc[mi][ni], a[cur][mi], b[cur][ni]);
        }
    }

#pragma unroll
    for (int mi = 0; mi < 2; mi++) {
        int row = m0 + mi * 16 + (lane >> 2);
        const float inv0 = invs[mi * 16 + (lane >> 2)];
        const float inv1 = invs[mi * 16 + 8 + (lane >> 2)];
#pragma unroll
        for (int ni = 0; ni < 4; ni++) {
            int col = n0 + wn * 32 + ni * 8 + ((lane & 3) << 1);
            store_out(out, row,     col,     acc[mi][ni][0] * inv0);
            store_out(out, row,     col + 1, acc[mi][ni][1] * inv0);
            store_out(out, row + 8, col,     acc[mi][ni][2] * inv1);
            store_out(out, row + 8, col + 1, acc[mi][ni][3] * inv1);
        }
    }
}

// ---------------- launch ----------------
extern "C" void kernel_launch(void* const* d_in, const int* in_sizes, int n_in,
                              void* d_out, int out_size) {
    const float* z1 = (const float*)d_in[0];
    const float* z2 = (const float*)d_in[1];
    float* out = (float*)d_out;

    cudaFuncSetAttribute(gemm_qk_kernel,
                         cudaFuncAttributeMaxDynamicSharedMemorySize, SMEM_BYTES);
    cudaFuncSetAttribute(gemm_av_kernel,
                         cudaFuncAttributeMaxDynamicSharedMemorySize, SMEM_BYTES);

    transpose_kernel<<<dim3(HW / 32, KC / 32, 2), 256>>>(z1, z2);
    gemm_qk_kernel<<<dim3(NPAD / BN, M / BM), 64, SMEM_BYTES>>>();   // 88x5 = 440
    gemm_av_kernel<<<dim3(D / BN, M / BM), 64, SMEM_BYTES>>>(out);   // 80x5 = 400
}

// round 17
// speedup vs baseline: 1.2203x; 1.0142x over previous
#include <cuda_runtime.h>
#include <cuda_fp16.h>
#include <cstdint>

// ---------------- problem constants ----------------
constexpr int KC = 128, KH = 10, KW = 4;
constexpr int H = 100, W = 64;
constexpr int HW = H * W;                  // 6400
constexpr int NH = 10, NW = 16;
constexpr int M = NH * NW;                 // 160 q rows
constexpr int HK = H - KH + 1;             // 91
constexpr int WK = W - KW + 1;             // 61
constexpr int NKV = HK * WK;               // 5551
constexpr int NPAD = 5632;                 // 88*64
constexpr int D = KC * KH * KW;            // 5120
constexpr int NT1 = NPAD / 64;             // 88 qk n-tiles

// Feature ordering: d = (i*4+j)*128 + c   (ij-major, channel-fast)

// ---------------- scratch (~5 MB, L2-hot) ----------------
__device__ __half g_z1t[(size_t)HW * KC];
__device__ __half g_z2t[(size_t)HW * KC];
__device__ __half g_attn[(size_t)M * NPAD];
__device__ float  g_rsum2[M][NT1];

// ---------------- ptx helpers ----------------
__device__ __forceinline__ uint32_t smem_u32(const void* p) {
    return (uint32_t)__cvta_generic_to_shared(p);
}
__device__ __forceinline__ void ldsm_x4(uint32_t& r0, uint32_t& r1, uint32_t& r2,
                                        uint32_t& r3, uint32_t a) {
    asm volatile("ldmatrix.sync.aligned.m8n8.x4.shared.b16 {%0,%1,%2,%3}, [%4];"
                 : "=r"(r0), "=r"(r1), "=r"(r2), "=r"(r3) : "r"(a));
}
__device__ __forceinline__ void ldsm_x4_t(uint32_t& r0, uint32_t& r1, uint32_t& r2,
                                          uint32_t& r3, uint32_t a) {
    asm volatile("ldmatrix.sync.aligned.m8n8.x4.trans.shared.b16 {%0,%1,%2,%3}, [%4];"
                 : "=r"(r0), "=r"(r1), "=r"(r2), "=r"(r3) : "r"(a));
}
__device__ __forceinline__ void mma16816(float* c, const uint32_t* a, const uint32_t* b) {
    asm volatile("mma.sync.aligned.m16n8k16.row.col.f32.f16.f16.f32 "
                 "{%0,%1,%2,%3}, {%4,%5,%6,%7}, {%8,%9}, {%0,%1,%2,%3};"
                 : "+f"(c[0]), "+f"(c[1]), "+f"(c[2]), "+f"(c[3])
                 : "r"(a[0]), "r"(a[1]), "r"(a[2]), "r"(a[3]),
                   "r"(b[0]), "r"(b[1]));
}
// fp16-accumulator HMMA (2x rate vs f32 acc on legacy tensor path)
__device__ __forceinline__ void mma16816_h(uint32_t* c, const uint32_t* a, const uint32_t* b) {
    asm volatile("mma.sync.aligned.m16n8k16.row.col.f16.f16.f16.f16 "
                 "{%0,%1}, {%2,%3,%4,%5}, {%6,%7}, {%0,%1};"
                 : "+r"(c[0]), "+r"(c[1])
                 : "r"(a[0]), "r"(a[1]), "r"(a[2]), "r"(a[3]),
                   "r"(b[0]), "r"(b[1]));
}
__device__ __forceinline__ void cpasync16_ca(uint32_t s, const void* g) {
    asm volatile("cp.async.ca.shared.global [%0], [%1], 16;" :: "r"(s), "l"(g));
}
#define CP_COMMIT() asm volatile("cp.async.commit_group;")
#define CP_WAIT(n)  asm volatile("cp.async.wait_group %0;" :: "n"(n))

__device__ __forceinline__ int kv_base(int n) {
    if (n >= NKV) return 0;
    int h = n / WK;
    int w = n - h * WK;
    return h * W + w;
}

// ------- kernel 0: transpose z1/z2 [c][hw] f32 -> [hw][c] f16 -------
__global__ __launch_bounds__(256) void transpose_kernel(const float* __restrict__ z1,
                                                        const float* __restrict__ z2) {
    __shared__ float tile[32][33];
    const float* src = blockIdx.z ? z2 : z1;
    __half* dst      = blockIdx.z ? g_z2t : g_z1t;
    const int hw0 = blockIdx.x * 32;
    const int c0  = blockIdx.y * 32;
    const int tx = threadIdx.x & 31;
    const int ty = threadIdx.x >> 5;
#pragma unroll
    for (int k = 0; k < 4; k++)
        tile[ty + 8 * k][tx] = src[(size_t)(c0 + ty + 8 * k) * HW + hw0 + tx];
    __syncthreads();
#pragma unroll
    for (int k = 0; k < 4; k++)
        dst[(size_t)(hw0 + ty + 8 * k) * KC + c0 + tx] =
            __float2half(tile[tx][ty + 8 * k]);
}

// -------- GEMM tiling: CTA 32(M) x 64(N), 64 threads = 2 warps ----
constexpr int BM  = 32;
constexpr int BN  = 64;
constexpr int BK  = 64;
constexpr int LDS = 72;
constexpr int STAGES = 4;
constexpr int A_HALVES = BM * LDS;
constexpr int B_HALVES = BN * LDS;
constexpr int STAGE_HALVES = A_HALVES + B_HALVES;
constexpr int SMEM_BYTES = STAGES * STAGE_HALVES * 2;   // 55296

// ------ kernel 1: attn_unnorm = exp(q @ kv^T / D), fp16 accumulators ------
__global__ __launch_bounds__(64, 4) void gemm_qk_kernel() {
    extern __shared__ __align__(16) __half sm[];
    __shared__ float rsm[2][32];
    const int n0   = blockIdx.x * BN;
    const int m0   = blockIdx.y * BM;
    const int tid  = threadIdx.x;
    const int wn   = tid >> 5, lane = tid & 31;
    constexpr int KT = D / BK;                   // 80
    const int c8 = (tid & 7) << 3;

    int baseq[4];
#pragma unroll
    for (int it = 0; it < 4; it++) {
        int m = m0 + (tid >> 3) + it * 8;
        baseq[it] = (m >> 4) * (KH * W) + (m & 15) * KW;
    }
    int baseb[8];
#pragma unroll
    for (int it = 0; it < 8; it++)
        baseb[it] = kv_base(n0 + (tid >> 3) + it * 8);

    auto load_stage = [&](int s, int kt) {
        const int ij    = kt >> 1;
        const int c0    = (kt & 1) << 6;
        const int ijoff = ((ij >> 2) << 6) + (ij & 3);
        __half* As = sm + s * STAGE_HALVES;
        __half* Bs = As + A_HALVES;
        const int rA = tid >> 3;
#pragma unroll
        for (int it = 0; it < 4; it++) {
            cpasync16_ca(smem_u32(&As[(rA + it * 8) * LDS + c8]),
                         &g_z1t[(size_t)(baseq[it] + ijoff) * KC + c0 + c8]);
        }
#pragma unroll
        for (int it = 0; it < 8; it++) {
            cpasync16_ca(smem_u32(&Bs[(rA + it * 8) * LDS + c8]),
                         &g_z2t[(size_t)(baseb[it] + ijoff) * KC + c0 + c8]);
        }
    };

#pragma unroll
    for (int s = 0; s < STAGES - 1; s++) { load_stage(s, s); CP_COMMIT(); }

    uint32_t hacc[2][4][2] = {};                 // fp16x2 accumulators
    uint32_t a[2][2][4], b[2][4][2];

    auto load_frags = [&](const __half* As, const __half* Bs, int ks, int buf) {
#pragma unroll
        for (int mi = 0; mi < 2; mi++) {
            int r = mi * 16 + (lane & 15);
            int c = ks * 16 + (lane >> 4) * 8;
            ldsm_x4(a[buf][mi][0], a[buf][mi][1], a[buf][mi][2], a[buf][mi][3],
                    smem_u32(&As[r * LDS + c]));
        }
#pragma unroll
        for (int nb = 0; nb < 2; nb++) {
            int r = wn * 32 + nb * 16 + (lane & 7) + (lane >> 4) * 8;
            int c = ks * 16 + ((lane >> 3) & 1) * 8;
            uint32_t r0, r1, r2, r3;
            ldsm_x4(r0, r1, r2, r3, smem_u32(&Bs[r * LDS + c]));
            b[buf][nb * 2][0] = r0; b[buf][nb * 2][1] = r1;
            b[buf][nb * 2 + 1][0] = r2; b[buf][nb * 2 + 1][1] = r3;
        }
    };

    for (int kt = 0; kt < KT; kt++) {
        CP_WAIT(STAGES - 2);
        __syncthreads();
        int nxt = kt + STAGES - 1;
        if (nxt < KT) load_stage(nxt & (STAGES - 1), nxt);
        CP_COMMIT();

        const __half* As = sm + (kt & (STAGES - 1)) * STAGE_HALVES;
        const __half* Bs = As + A_HALVES;
        load_frags(As, Bs, 0, 0);
#pragma unroll
        for (int ks = 0; ks < BK / 16; ks++) {
            const int cur = ks & 1;
            if (ks < BK / 16 - 1) load_frags(As, Bs, ks + 1, cur ^ 1);
#pragma unroll
            for (int mi = 0; mi < 2; mi++)
#pragma unroll
                for (int ni = 0; ni < 4; ni++)
                    mma16816_h(hacc[mi][ni], a[cur][mi], b[cur][ni]);
        }
    }

    // epilogue: unpack fp16 accs, p = exp(s/D), mask pads, store + partials
    const float scale = 1.0f / (float)D;
    float rp[2][2] = {};
#pragma unroll
    for (int mi = 0; mi < 2; mi++)
#pragma unroll
        for (int ni = 0; ni < 4; ni++) {
            int row = m0 + mi * 16 + (lane >> 2);
            int col = n0 + wn * 32 + ni * 8 + ((lane & 3) << 1);
            float2 f0 = __half22float2(*reinterpret_cast<__half2*>(&hacc[mi][ni][0]));
            float2 f1 = __half22float2(*reinterpret_cast<__half2*>(&hacc[mi][ni][1]));
            float p00 = (col     < NKV) ? __expf(f0.x * scale) : 0.f;
            float p01 = (col + 1 < NKV) ? __expf(f0.y * scale) : 0.f;
            float p10 = (col     < NKV) ? __expf(f1.x * scale) : 0.f;
            float p11 = (col + 1 < NKV) ? __expf(f1.y * scale) : 0.f;
            *reinterpret_cast<__half2*>(&g_attn[(size_t)row * NPAD + col]) =
                __floats2half2_rn(p00, p01);
            *reinterpret_cast<__half2*>(&g_attn[(size_t)(row + 8) * NPAD + col]) =
                __floats2half2_rn(p10, p11);
            rp[mi][0] += p00 + p01;
            rp[mi][1] += p10 + p11;
        }
#pragma unroll
    for (int o = 1; o < 4; o <<= 1) {
#pragma unroll
        for (int mi = 0; mi < 2; mi++) {
            rp[mi][0] += __shfl_xor_sync(0xffffffffu, rp[mi][0], o);
            rp[mi][1] += __shfl_xor_sync(0xffffffffu, rp[mi][1], o);
        }
    }
    if ((lane & 3) == 0) {
        int r = lane >> 2;
#pragma unroll
        for (int mi = 0; mi < 2; mi++) {
            rsm[wn][mi * 16 + r]     = rp[mi][0];
            rsm[wn][mi * 16 + 8 + r] = rp[mi][1];
        }
    }
    __syncthreads();
    if (tid < 32)
        g_rsum2[m0 + tid][blockIdx.x] = rsm[0][tid] + rsm[1][tid];
}

// ------ kernel 2: out = (attn_unnorm @ kv) * inv[row] (fp32 acc) ------
__device__ __forceinline__ void store_out(float* __restrict__ out, int m, int d, float v) {
    int ij = d >> 7;
    int c  = d & 127;
    int i  = ij >> 2;
    int j  = ij & 3;
    int ih = m >> 4;
    int iw = m & 15;
    out[(c * H + ih * KH + i) * W + iw * KW + j] = v;
}

__global__ __launch_bounds__(64, 4) void gemm_av_kernel(float* __restrict__ out) {
    extern __shared__ __align__(16) __half sm[];
    __shared__ float invs[32];
    const int n0   = blockIdx.x * BN;            // over D
    const int m0   = blockIdx.y * BM;
    const int tid  = threadIdx.x;
    const int wn   = tid >> 5, lane = tid & 31;
    constexpr int KT = NPAD / BK;                // 88
    const int c8 = (tid & 7) << 3;

    const int ij_cta    = n0 >> 7;
    const int c0_cta    = n0 & 127;
    const int ijoff_cta = ((ij_cta >> 2) << 6) + (ij_cta & 3);

    if (tid < 32) {
        float s = 0.f;
#pragma unroll 8
        for (int t = 0; t < NT1; t++) s += g_rsum2[m0 + tid][t];
        invs[tid] = 1.0f / s;
    }

    auto load_stage = [&](int s, int kt) {
        const int k0 = kt * BK;
        __half* As = sm + s * STAGE_HALVES;
        __half* Bs = As + A_HALVES;
        const int rA = tid >> 3;
#pragma unroll
        for (int it = 0; it < 4; it++) {
            cpasync16_ca(smem_u32(&As[(rA + it * 8) * LDS + c8]),
                         &g_attn[(size_t)(m0 + rA + it * 8) * NPAD + k0 + c8]);
        }
#pragma unroll
        for (int it = 0; it < 8; it++) {
            int n = k0 + rA + it * 8;
            int base = kv_base(n);
            cpasync16_ca(smem_u32(&Bs[(rA + it * 8) * LDS + c8]),
                         &g_z2t[(size_t)(base + ijoff_cta) * KC + c0_cta + c8]);
        }
    };

#pragma unroll
    for (int s = 0; s < STAGES - 1; s++) { load_stage(s, s); CP_COMMIT(); }

    float acc[2][4][4] = {};
    uint32_t a[2][2][4], b[2][4][2];

    auto load_frags = [&](const __half* As, const __half* Bs, int ks, int buf) {
#pragma unroll
        for (int mi = 0; mi < 2; mi++) {
            int r = mi * 16 + (lane & 15);
            int c = ks * 16 + (lane >> 4) * 8;
            ldsm_x4(a[buf][mi][0], a[buf][mi][1], a[buf][mi][2], a[buf][mi][3],
                    smem_u32(&As[r * LDS + c]));
        }
#pragma unroll
        for (int nb = 0; nb < 2; nb++) {
            int r = ks * 16 + (lane & 7) + ((lane >> 3) & 1) * 8;
            int c = wn * 32 + nb * 16 + (lane >> 4) * 8;
            uint32_t r0, r1, r2, r3;
            ldsm_x4_t(r0, r1, r2, r3, smem_u32(&Bs[r * LDS + c]));
            b[buf][nb * 2][0] = r0; b[buf][nb * 2][1] = r1;
            b[buf][nb * 2 + 1][0] = r2; b[buf][nb * 2 + 1][1] = r3;
        }
    };

    for (int kt = 0; kt < KT; kt++) {
        CP_WAIT(STAGES - 2);
        __syncthreads();
        int nxt = kt + STAGES - 1;
        if (nxt < KT) load_stage(nxt & (STAGES - 1), nxt);
        CP_COMMIT();

        const __half* As = sm + (kt & (STAGES - 1)) * STAGE_HALVES;
        const __half* Bs = As + A_HALVES;
        load_frags(As, Bs, 0, 0);
#pragma unroll
        for (int ks = 0; ks < BK / 16; ks++) {
            const int cur = ks & 1;
            if (ks < BK / 16 - 1) load_frags(As, Bs, ks + 1, cur ^ 1);
#pragma unroll
            for (int mi = 0; mi < 2; mi++)
#pragma unroll
                for (int ni = 0; ni < 4; ni++)
                    mma16816(acc[mi][ni], a[cur][mi], b[cur][ni]);
        }
    }

#pragma unroll
    for (int mi = 0; mi < 2; mi++) {
        int row = m0 + mi * 16 + (lane >> 2);
        const float inv0 = invs[mi * 16 + (lane >> 2)];
        const float inv1 = invs[mi * 16 + 8 + (lane >> 2)];
#pragma unroll
        for (int ni = 0; ni < 4; ni++) {
            int col = n0 + wn * 32 + ni * 8 + ((lane & 3) << 1);
            store_out(out, row,     col,     acc[mi][ni][0] * inv0);
            store_out(out, row,     col + 1, acc[mi][ni][1] * inv0);
            store_out(out, row + 8, col,     acc[mi][ni][2] * inv1);
            store_out(out, row + 8, col + 1, acc[mi][ni][3] * inv1);
        }
    }
}

// ---------------- launch ----------------
extern "C" void kernel_launch(void* const* d_in, const int* in_sizes, int n_in,
                              void* d_out, int out_size) {
    const float* z1 = (const float*)d_in[0];
    const float* z2 = (const float*)d_in[1];
    float* out = (float*)d_out;

    cudaFuncSetAttribute(gemm_qk_kernel,
                         cudaFuncAttributeMaxDynamicSharedMemorySize, SMEM_BYTES);
    cudaFuncSetAttribute(gemm_av_kernel,
                         cudaFuncAttributeMaxDynamicSharedMemorySize, SMEM_BYTES);

    transpose_kernel<<<dim3(HW / 32, KC / 32, 2), 256>>>(z1, z2);
    gemm_qk_kernel<<<dim3(NPAD / BN, M / BM), 64, SMEM_BYTES>>>();   // 88x5 = 440
    gemm_av_kernel<<<dim3(D / BN, M / BM), 64, SMEM_BYTES>>>(out);   // 80x5 = 400
}